// round 1
// baseline (speedup 1.0000x reference)
#include <cuda_runtime.h>
#include <cstddef>

#define NSPEC 10
#define KCH   64
#define D     9
#define NA1   3
#define NA2   8
#define NA3   18
#define ATOT  29
#define NEK   (NSPEC * KCH)        // 640 (species, channel) combos
#define CROW  12                   // padded l-dimension (9 data + c2/c1 slot at 9 + 2 pad)
#define CJ    10                   // extended j-dimension (9 data + c1 row)
#define CBLK  (9 * 9 * CJ * CROW)  // floats per (e,k) coefficient tile = 9720

// Scratch (device globals — allocation-free per harness rules)
__device__ float g_wp[NSPEC * ATOT * KCH];          // wp[z][b][k]
__device__ float g_C[(size_t)NEK * CBLK];           // Chat[ek][o][i][j][l]

// ---------------------------------------------------------------------------
// Kernel A: wp[z][b][k] = sum_a w[z][a][k] * proj[a][b]
// ---------------------------------------------------------------------------
__global__ void wp_kernel(const float* __restrict__ w,
                          const float* __restrict__ proj) {
    int tid = blockIdx.x * blockDim.x + threadIdx.x;
    if (tid >= NSPEC * ATOT * KCH) return;
    int k = tid % KCH;
    int b = (tid / KCH) % ATOT;
    int z = tid / (KCH * ATOT);
    float s = 0.f;
#pragma unroll
    for (int a = 0; a < ATOT; a++)
        s = fmaf(w[(z * ATOT + a) * KCH + k], proj[a * ATOT + b], s);
    g_wp[tid] = s;  // tid == (z*ATOT+b)*KCH + k
}

// ---------------------------------------------------------------------------
// Kernel B: build Chat[ek][o][i][j][l]:
//   j<9, l<9 : C3 = sum_a U3[o,i,j,l,a] * wp[e, 11+a, k]
//   j<9, l=9 : C2 = sum_a U2[o,i,j,a]   * wp[e,  3+a, k]
//   j=9, l=9 : C1 = sum_a U1[o,i,a]     * wp[e,    a, k]
//   everything else 0.  One block per (o,i,j); 640 threads sweep (e,k).
// ---------------------------------------------------------------------------
__global__ void coeff_kernel(const float* __restrict__ U1,
                             const float* __restrict__ U2,
                             const float* __restrict__ U3) {
    int bid = blockIdx.x;            // (o*9+i)*10 + j, 810 blocks
    int j = bid % CJ;
    int i = (bid / CJ) % 9;
    int o = bid / (CJ * 9);

    __shared__ float u3s[9 * NA3];
    __shared__ float u2s[NA2];
    __shared__ float u1s[NA1];
    if (j < 9) {
        for (int t = threadIdx.x; t < 9 * NA3; t += blockDim.x)
            u3s[t] = U3[(size_t)(((o * 9 + i) * 9 + j) * 9) * NA3 + t];
        if (threadIdx.x < NA2)
            u2s[threadIdx.x] = U2[((o * 9 + i) * 9 + j) * NA2 + threadIdx.x];
    } else {
        if (threadIdx.x < NA1)
            u1s[threadIdx.x] = U1[(o * 9 + i) * NA1 + threadIdx.x];
    }
    __syncthreads();

    int ek = threadIdx.x;            // blockDim == 640
    int e = ek / KCH, k = ek % KCH;

    float res[CROW];
#pragma unroll
    for (int l = 0; l < CROW; l++) res[l] = 0.f;

    if (j < 9) {
        float wp3[NA3];
#pragma unroll
        for (int a = 0; a < NA3; a++)
            wp3[a] = g_wp[(e * ATOT + NA1 + NA2 + a) * KCH + k];
#pragma unroll
        for (int l = 0; l < 9; l++) {
            float s = 0.f;
#pragma unroll
            for (int a = 0; a < NA3; a++)
                s = fmaf(u3s[l * NA3 + a], wp3[a], s);
            res[l] = s;
        }
        float s2 = 0.f;
#pragma unroll
        for (int a = 0; a < NA2; a++)
            s2 = fmaf(u2s[a], g_wp[(e * ATOT + NA1 + a) * KCH + k], s2);
        res[9] = s2;
    } else {
        float s1 = 0.f;
#pragma unroll
        for (int a = 0; a < NA1; a++)
            s1 = fmaf(u1s[a], g_wp[(e * ATOT + a) * KCH + k], s1);
        res[9] = s1;
    }

    float4* d4 = (float4*)(g_C + (size_t)ek * CBLK + (size_t)bid * CROW);
    d4[0] = make_float4(res[0], res[1], res[2], res[3]);
    d4[1] = make_float4(res[4], res[5], res[6], res[7]);
    d4[2] = make_float4(res[8], res[9], res[10], res[11]);
}

// ---------------------------------------------------------------------------
// Kernel C: evaluate. One block per (k, e). 9 warps; warp w -> output o=w,
// lane -> one n of this species. Coefficient tile in smem, broadcast LDS.
//   out[n,k,o] = sum_i v_i * sum_{j<10} vhat_j * sum_{l<10} Chat[o,i,j,l]*vhat_l
// with vhat = (v0..v8, 1).
// ---------------------------------------------------------------------------
__global__ void __launch_bounds__(288)
eval_kernel(const float* __restrict__ x,
            const int* __restrict__ counts,
            float* __restrict__ out) {
    int k = blockIdx.x;
    int e = blockIdx.y;

    __shared__ float Cs[CBLK];
    {
        const float4* src = (const float4*)(g_C + (size_t)(e * KCH + k) * CBLK);
        float4* dst = (float4*)Cs;
        for (int t = threadIdx.x; t < CBLK / 4; t += blockDim.x)
            dst[t] = src[t];
    }

    int start = 0;
#pragma unroll
    for (int t = 0; t < NSPEC; t++) {
        int c = counts[t];
        if (t < e) start += c;
    }
    int cnt = counts[e];
    __syncthreads();

    int o = threadIdx.x >> 5;         // warp id = output index (9 warps)
    int lane = threadIdx.x & 31;
    const float* Co = Cs + o * 9 * CJ * CROW;

    for (int base = 0; base < cnt; base += 32) {
        int nl = base + lane;
        if (nl < cnt) {
            int n = start + nl;
            const float* xp = x + ((size_t)n * KCH + k) * D;
            float v[10];
#pragma unroll
            for (int t = 0; t < 9; t++) v[t] = xp[t];
            v[9] = 1.f;

            float acc = 0.f;
#pragma unroll
            for (int i = 0; i < 9; i++) {
                const float* Ci = Co + i * CJ * CROW;
                float ti = 0.f;
#pragma unroll
                for (int jj = 0; jj < CJ; jj++) {
                    const float4 c0 = *(const float4*)(Ci + jj * CROW);
                    const float4 c1 = *(const float4*)(Ci + jj * CROW + 4);
                    const float2 c2 = *(const float2*)(Ci + jj * CROW + 8);
                    float t;
                    t = c0.x * v[0];
                    t = fmaf(c0.y, v[1], t);
                    t = fmaf(c0.z, v[2], t);
                    t = fmaf(c0.w, v[3], t);
                    t = fmaf(c1.x, v[4], t);
                    t = fmaf(c1.y, v[5], t);
                    t = fmaf(c1.z, v[6], t);
                    t = fmaf(c1.w, v[7], t);
                    t = fmaf(c2.x, v[8], t);
                    t = fmaf(c2.y, v[9], t);      // c2/c1 fold-in (vhat_9 = 1)
                    ti = fmaf(t, v[jj], ti);
                }
                acc = fmaf(ti, v[i], acc);
            }
            out[((size_t)n * KCH + k) * D + o] = acc;
        }
    }
}

// ---------------------------------------------------------------------------
extern "C" void kernel_launch(void* const* d_in, const int* in_sizes, int n_in,
                              void* d_out, int out_size) {
    const float* x      = (const float*)d_in[0];
    const int*   counts = (const int*)  d_in[1];
    const float* w      = (const float*)d_in[2];
    const float* proj   = (const float*)d_in[3];
    const float* U1     = (const float*)d_in[4];
    const float* U2     = (const float*)d_in[5];
    const float* U3     = (const float*)d_in[6];
    float* out = (float*)d_out;

    wp_kernel<<<(NSPEC * ATOT * KCH + 255) / 256, 256>>>(w, proj);
    coeff_kernel<<<9 * 9 * CJ, NEK>>>(U1, U2, U3);
    dim3 grid(KCH, NSPEC);
    eval_kernel<<<grid, 288>>>(x, counts, out);
}

// round 2
// speedup vs baseline: 1.6714x; 1.6714x over previous
#include <cuda_runtime.h>
#include <cstddef>

#define NSPEC 10
#define KCH   64
#define D     9
#define NA1   3
#define NA2   8
#define NA3   18
#define ATOT  29
#define NEK   (NSPEC * KCH)   // 640 (species, channel) combos
#define NM    220             // C(12,3): monomials i<=j<=l over 10 vars (v9 == 1)
#define ROWF  12              // padded floats per monomial row (9 outputs + 3 pad)

// Scratch (device globals — allocation-free per harness rules)
// S[ek][m][ROWF]: symmetrized coefficient, 9 outputs per monomial.
__device__ float g_S[(size_t)NEK * NM * ROWF];   // 6.76 MB

// ---------------------------------------------------------------------------
// packed f32x2 FMA helpers (sm_103a FFMA2 — PTX only)
// ---------------------------------------------------------------------------
__device__ __forceinline__ void ffma2(unsigned long long& d,
                                      unsigned long long a,
                                      unsigned long long b) {
    asm("fma.rn.f32x2 %0, %1, %2, %0;" : "+l"(d) : "l"(a), "l"(b));
}
__device__ __forceinline__ unsigned long long dup_f32(float t) {
    unsigned long long r;
    asm("mov.b64 %0, {%1, %1};" : "=l"(r) : "r"(__float_as_uint(t)));
    return r;
}
__device__ __forceinline__ void unpack2(unsigned long long p, float& lo, float& hi) {
    unsigned a, b;
    asm("mov.b64 {%0, %1}, %2;" : "=r"(a), "=r"(b) : "l"(p));
    lo = __uint_as_float(a); hi = __uint_as_float(b);
}

// ---------------------------------------------------------------------------
// Kernel 1: fused wp + symmetrized coefficients. One block per monomial m.
//   m -> sorted triple (mi<=mj<=ml) over vars 0..9 (9 == virtual const var).
//   deg3 (ml<9): Us[o][a] = sum over distinct perms of (mi,mj,ml) of U3[o,...,a]
//   deg2 (ml==9, mj<9): perms of (mi,mj) over U2
//   deg1 (mj==9, mi<9): U1[o,mi,a]
//   Then per (e,k): S[ek][m][o] = sum_a Us[o][a] * wp[e, aoff+a, k],
//   with wp recomputed in-block from w and projection.
// ---------------------------------------------------------------------------
__global__ void __launch_bounds__(NEK)
coeff_kernel(const float* __restrict__ w,
             const float* __restrict__ proj,
             const float* __restrict__ U1,
             const float* __restrict__ U2,
             const float* __restrict__ U3) {
    const int m = blockIdx.x;
    // reconstruct sorted triple
    int mi = 9, mj = 9, ml = 9;
    {
        int c = 0;
        for (int i = 0; i < 10; i++)
            for (int j = i; j < 10; j++)
                for (int l = j; l < 10; l++) {
                    if (c == m) { mi = i; mj = j; ml = l; }
                    c++;
                }
    }
    const int deg  = (ml < 9) ? 3 : (mj < 9) ? 2 : (mi < 9) ? 1 : 0;
    const int aoff = (deg == 3) ? (NA1 + NA2) : (deg == 2) ? NA1 : 0;
    const int acnt = (deg == 3) ? NA3 : (deg == 2) ? NA2 : (deg == 1) ? NA1 : 0;

    __shared__ float Us[9 * NA3];      // [o][a]
    __shared__ float Ps[ATOT * NA3];   // proj[a][aoff + b], b < acnt

    const int t = threadIdx.x;

    if (t < 9 * NA3) {
        int o = t / NA3, a = t % NA3;
        float s = 0.f;
        if (deg == 3) {
            int P[6][3] = {{mi,mj,ml},{mi,ml,mj},{mj,mi,ml},
                           {mj,ml,mi},{ml,mi,mj},{ml,mj,mi}};
#pragma unroll
            for (int p = 0; p < 6; p++) {
                bool dup = false;
#pragma unroll
                for (int q = 0; q < 6; q++)
                    if (q < p && P[q][0] == P[p][0] && P[q][1] == P[p][1] &&
                        P[q][2] == P[p][2]) dup = true;
                if (!dup)
                    s += U3[((((size_t)o * 9 + P[p][0]) * 9 + P[p][1]) * 9 + P[p][2]) * NA3 + a];
            }
        } else if (deg == 2 && a < NA2) {
            s = U2[(((size_t)o * 9 + mi) * 9 + mj) * NA2 + a];
            if (mi != mj)
                s += U2[(((size_t)o * 9 + mj) * 9 + mi) * NA2 + a];
        } else if (deg == 1 && a < NA1) {
            s = U1[((size_t)o * 9 + mi) * NA1 + a];
        }
        Us[t] = s;
    }
    if (t < ATOT * acnt) {
        int a = t / acnt, b = t % acnt;
        Ps[a * NA3 + b] = proj[a * ATOT + aoff + b];
    }
    __syncthreads();

    // t = ek in [0, 640)
    const int e = t >> 6, k = t & 63;
    float wr[ATOT];
#pragma unroll
    for (int a = 0; a < ATOT; a++)
        wr[a] = w[((size_t)e * ATOT + a) * KCH + k];

    float c9[9];
#pragma unroll
    for (int o = 0; o < 9; o++) c9[o] = 0.f;

    for (int b = 0; b < acnt; b++) {
        float wpb = 0.f;
#pragma unroll
        for (int a = 0; a < ATOT; a++)
            wpb = fmaf(wr[a], Ps[a * NA3 + b], wpb);
#pragma unroll
        for (int o = 0; o < 9; o++)
            c9[o] = fmaf(Us[o * NA3 + b], wpb, c9[o]);
    }

    float* dst = g_S + ((size_t)t * NM + m) * ROWF;
    ((float4*)dst)[0] = make_float4(c9[0], c9[1], c9[2], c9[3]);
    ((float4*)dst)[1] = make_float4(c9[4], c9[5], c9[6], c9[7]);
    dst[8] = c9[8];
}

// ---------------------------------------------------------------------------
// Kernel 2: evaluate. One block per (k, e), 128 threads, lane = one n.
//   vhat = (x[n,k,0..8], 1);   out[n,k,o] = sum_m S[ek][m][o] * monomial_m(vhat)
//   Coefficient tile broadcast from smem; 9 accumulators as 4x f32x2 + 1 scalar.
// ---------------------------------------------------------------------------
__global__ void __launch_bounds__(128)
eval_kernel(const float* __restrict__ x,
            const int* __restrict__ counts,
            float* __restrict__ out) {
    const int k = blockIdx.x;
    const int e = blockIdx.y;
    const int ek = e * KCH + k;

    __shared__ __align__(16) float Cs[NM * ROWF];
    {
        const float4* src = (const float4*)(g_S + (size_t)ek * NM * ROWF);
        float4* dst = (float4*)Cs;
        for (int t = threadIdx.x; t < NM * ROWF / 4; t += blockDim.x)
            dst[t] = src[t];
    }

    int start = 0, cnt = 0;
#pragma unroll
    for (int t = 0; t < NSPEC; t++) {
        int c = counts[t];
        if (t < e) start += c;
        if (t == e) cnt = c;
    }
    __syncthreads();

    for (int base = 0; base < cnt; base += blockDim.x) {
        int nl = base + threadIdx.x;
        if (nl >= cnt) break;
        int n = start + nl;
        const float* xp = x + ((size_t)n * KCH + k) * D;
        float v[10];
#pragma unroll
        for (int t = 0; t < 9; t++) v[t] = xp[t];
        v[9] = 1.f;

        unsigned long long a01 = 0, a23 = 0, a45 = 0, a67 = 0;
        float a8 = 0.f;

        int m = 0;
#pragma unroll
        for (int i = 0; i < 10; i++) {
#pragma unroll
            for (int j = i; j < 10; j++) {
                float pij = v[i] * v[j];
#pragma unroll
                for (int l = j; l < 10; l++) {
                    float tm = pij * v[l];
                    const float* row = Cs + m * ROWF;
                    ulonglong2 cA = *(const ulonglong2*)row;        // o0..3
                    ulonglong2 cB = *(const ulonglong2*)(row + 4);  // o4..7
                    float c8 = row[8];
                    unsigned long long tt = dup_f32(tm);
                    ffma2(a01, cA.x, tt);
                    ffma2(a23, cA.y, tt);
                    ffma2(a45, cB.x, tt);
                    ffma2(a67, cB.y, tt);
                    a8 = fmaf(c8, tm, a8);
                    m++;
                }
            }
        }

        float r[9];
        unpack2(a01, r[0], r[1]);
        unpack2(a23, r[2], r[3]);
        unpack2(a45, r[4], r[5]);
        unpack2(a67, r[6], r[7]);
        r[8] = a8;

        float* op = out + ((size_t)n * KCH + k) * D;
#pragma unroll
        for (int o = 0; o < 9; o++) op[o] = r[o];
    }
}

// ---------------------------------------------------------------------------
extern "C" void kernel_launch(void* const* d_in, const int* in_sizes, int n_in,
                              void* d_out, int out_size) {
    const float* x      = (const float*)d_in[0];
    const int*   counts = (const int*)  d_in[1];
    const float* w      = (const float*)d_in[2];
    const float* proj   = (const float*)d_in[3];
    const float* U1     = (const float*)d_in[4];
    const float* U2     = (const float*)d_in[5];
    const float* U3     = (const float*)d_in[6];
    float* out = (float*)d_out;

    coeff_kernel<<<NM, NEK>>>(w, proj, U1, U2, U3);
    dim3 grid(KCH, NSPEC);
    eval_kernel<<<grid, 128>>>(x, counts, out);
}